// round 3
// baseline (speedup 1.0000x reference)
#include <cuda_runtime.h>

// Problem constants
#define DD   128   // feature dim
#define CO   16    // output channels
#define PPV  16    // P*P
#define HG   32    // sqrt(N)
#define NB   32    // batch
#define NT   64    // n-rows per block
#define XPAD 132   // padded x/w row stride (floats)

// ---------------------------------------------------------------------------
// One block per (n-tile, b). 128 threads, grid (16, 32) = 512 blocks (1 wave).
//   Phase 0 : smem loads: x tile (64x128 -> pad 132), W (16x128 -> pad 132), mask.
//   Phase 1 : register-tiled GEMV: thread computes 2n x 4p dots (p strided by 4).
//             Threads 0..63 additionally compute cb[c][p] = emb[c].W[p]+bias[p].
//   Phase 2 : out[b,c,h*4+pr, l*4+pc] = (xw + cb) * mask; warp-wide 512B STG.128.
// ---------------------------------------------------------------------------
__global__ void __launch_bounds__(128, 4)
decoder_kernel(const float* __restrict__ x,
               const float* __restrict__ W,
               const float* __restrict__ emb,
               const float* __restrict__ bias,
               const float* __restrict__ mask,
               float* __restrict__ out) {
    __shared__ float xs[NT * XPAD];      // 33,792 B
    __shared__ float ws[PPV * XPAD];     //  8,448 B
    __shared__ float xw[NT * 20];        //  5,120 B (pad 20 -> conflict-free)
    __shared__ float cbs[CO * PPV];      //  1,024 B
    __shared__ float ms[CO];             //     64 B   (total 48,448 <= 48K)

    const int t  = threadIdx.x;
    const int nt = blockIdx.x;           // 0..15 : n-tile
    const int b  = blockIdx.y;           // 0..31 : batch

    // ---- Phase 0: cooperative loads -------------------------------------
    {
        // x rows n = nt*64 .. +63 are contiguous: 2048 float4, coalesced
        const float4* xg = reinterpret_cast<const float4*>(
            x + ((size_t)b * (HG * HG) + (size_t)nt * NT) * DD);
        #pragma unroll
        for (int k = 0; k < 16; k++) {
            int j   = t + k * 128;       // 0..2047
            int row = j >> 5;            // n_local
            int i   = j & 31;            // float4 chunk
            *reinterpret_cast<float4*>(&xs[row * XPAD + i * 4]) = xg[j];
        }
        // W: 512 float4 -> padded rows
        const float4* wg4 = reinterpret_cast<const float4*>(W);
        #pragma unroll
        for (int k = 0; k < 4; k++) {
            int j   = t + k * 128;       // 0..511
            int row = j >> 5;
            int i   = j & 31;
            *reinterpret_cast<float4*>(&ws[row * XPAD + i * 4]) = wg4[j];
        }
        if (t < CO) ms[t] = mask[b * CO + t];
    }
    __syncthreads();

    // ---- Phase 1: register-tiled GEMV (2n x 4p per thread) --------------
    {
        const int ngrp = t >> 2;         // 0..31 ; rows n0 = 2*ngrp, n0+1
        const int pg   = t & 3;          // p = pg + 4*j, j = 0..3
        const int n0   = ngrp * 2;

        float acc0[4] = {0.f, 0.f, 0.f, 0.f};
        float acc1[4] = {0.f, 0.f, 0.f, 0.f};
        #pragma unroll
        for (int i = 0; i < DD / 4; i++) {
            float4 xa = *reinterpret_cast<const float4*>(&xs[n0 * XPAD + i * 4]);
            float4 xb = *reinterpret_cast<const float4*>(&xs[(n0 + 1) * XPAD + i * 4]);
            #pragma unroll
            for (int j = 0; j < 4; j++) {
                float4 w = *reinterpret_cast<const float4*>(&ws[(pg + 4 * j) * XPAD + i * 4]);
                acc0[j] += xa.x * w.x + xa.y * w.y + xa.z * w.z + xa.w * w.w;
                acc1[j] += xb.x * w.x + xb.y * w.y + xb.z * w.z + xb.w * w.w;
            }
        }
        #pragma unroll
        for (int j = 0; j < 4; j++) {
            xw[n0 * 20 + pg + 4 * j]       = acc0[j];
            xw[(n0 + 1) * 20 + pg + 4 * j] = acc1[j];
        }
    }

    // ---- Phase 1b: cb[c][p] = emb[c].W[p] + bias[p]  (threads 0..63) ----
    if (t < 64) {
        const int c  = t >> 2;           // 0..15
        const int pg = t & 3;
        float acc[4] = {0.f, 0.f, 0.f, 0.f};
        const float4* eg = reinterpret_cast<const float4*>(emb + c * DD);
        #pragma unroll
        for (int i = 0; i < DD / 4; i++) {
            float4 e = __ldg(&eg[i]);    // L2-resident, shared by all blocks
            #pragma unroll
            for (int j = 0; j < 4; j++) {
                float4 w = *reinterpret_cast<const float4*>(&ws[(pg + 4 * j) * XPAD + i * 4]);
                acc[j] += e.x * w.x + e.y * w.y + e.z * w.z + e.w * w.w;
            }
        }
        #pragma unroll
        for (int j = 0; j < 4; j++)
            cbs[c * PPV + pg + 4 * j] = acc[j] + __ldg(&bias[pg + 4 * j]);
    }
    __syncthreads();

    // ---- Phase 2: expand over channels, mask, store ---------------------
    {
        const int w = t >> 5;            // warp 0..3
        const int l = t & 31;            // lane == n & 31 (col group)

        #pragma unroll
        for (int k = 0; k < 32; k++) {
            int rid = k * 4 + w;         // 0..127 : (c, pr, hgl)
            int c   = rid >> 3;
            int pr  = (rid >> 2) & 1 ? ((rid & 7) >> 1) : ((rid & 7) >> 1); // pr = (rid&7)>>1
            pr      = (rid & 7) >> 1;
            int hgl = rid & 1;

            int n_local = hgl * 32 + l;
            float4 xv  = *reinterpret_cast<const float4*>(&xw[n_local * 20 + pr * 4]);
            float4 cb4 = *reinterpret_cast<const float4*>(&cbs[c * PPV + pr * 4]);
            float  m   = ms[c];
            float4 o;
            o.x = (xv.x + cb4.x) * m;
            o.y = (xv.y + cb4.y) * m;
            o.z = (xv.z + cb4.z) * m;
            o.w = (xv.w + cb4.w) * m;

            int hg = nt * 2 + hgl;       // global h index
            size_t off = ((size_t)((b * CO + c) * (HG * 4) + hg * 4 + pr)) * (HG * 4)
                         + (size_t)l * 4;
            *reinterpret_cast<float4*>(out + off) = o;
        }
    }
}

// ---------------------------------------------------------------------------
extern "C" void kernel_launch(void* const* d_in, const int* in_sizes, int n_in,
                              void* d_out, int out_size) {
    const float* x    = (const float*)d_in[0];   // (32, 1024, 128)
    const float* mask = (const float*)d_in[1];   // (32, 16)
    const float* emb  = (const float*)d_in[2];   // (256, 128)
    const float* W    = (const float*)d_in[3];   // (16, 128)
    const float* bias = (const float*)d_in[4];   // (16,)
    float* out = (float*)d_out;                  // (32, 16, 128, 128)

    dim3 grid(HG * HG / NT, NB);                 // (16, 32) = 512 blocks
    decoder_kernel<<<grid, 128>>>(x, W, emb, bias, mask, out);
}

// round 5
// speedup vs baseline: 1.2507x; 1.2507x over previous
#include <cuda_runtime.h>

// Problem constants
#define DD   128   // feature dim
#define CO   16    // output channels
#define PPV  16    // P*P
#define HG   32    // sqrt(N)
#define NB   32    // batch
#define NT   64    // n-rows per K1 block

// Scratch (device globals: no allocation allowed)
__device__ float g_y[NB * 128 * 128];   // channel-independent image: 2 MiB, L2-resident
__device__ float g_cb[CO * PPV];        // emb[c].W[p] + bias[p]

// ---------------------------------------------------------------------------
// K1: y[b, h*4+j, w*4+pg] = x[b, n=h*32+w] . W[pg+4j]
//     128 threads, thread tile 2n x 4p. x read directly from gmem (one-touch,
//     no smem staging). W (8.5 KB padded) in smem. Block (0,0) also builds cb.
// ---------------------------------------------------------------------------
__global__ void __launch_bounds__(128, 8)
k1_gemv(const float* __restrict__ x,
        const float* __restrict__ W,
        const float* __restrict__ emb,
        const float* __restrict__ bias) {
    __shared__ float ws[PPV * 132];      // pad 132 -> conflict-free LDS.128

    const int t  = threadIdx.x;
    const int nt = blockIdx.x;           // 0..15
    const int b  = blockIdx.y;           // 0..31

    // load W -> smem (512 float4)
    {
        const float4* wg4 = reinterpret_cast<const float4*>(W);
        #pragma unroll
        for (int k = 0; k < 4; k++) {
            int j = t + k * 128;
            int row = j >> 5, i = j & 31;
            *reinterpret_cast<float4*>(&ws[row * 132 + i * 4]) = wg4[j];
        }
    }

    // cb table: only 64 threads of block (0,0); straight from gmem (L2)
    if (nt == 0 && b == 0 && t < 64) {
        const int c  = t >> 2;
        const int pg = t & 3;
        float acc[4] = {0.f, 0.f, 0.f, 0.f};
        const float4* eg = reinterpret_cast<const float4*>(emb + c * DD);
        #pragma unroll
        for (int i = 0; i < DD / 4; i++) {
            float4 e = __ldg(&eg[i]);
            #pragma unroll
            for (int j = 0; j < 4; j++) {
                float4 w = __ldg(reinterpret_cast<const float4*>(W + (pg + 4 * j) * DD) + i);
                acc[j] += e.x * w.x + e.y * w.y + e.z * w.z + e.w * w.w;
            }
        }
        #pragma unroll
        for (int j = 0; j < 4; j++)
            g_cb[c * PPV + pg + 4 * j] = acc[j] + __ldg(&bias[pg + 4 * j]);
    }
    __syncthreads();

    // register-tiled GEMV: rows n0, n0+1  x  cols {pg, pg+4, pg+8, pg+12}
    const int pg = t & 3;
    const int n0 = (t >> 2) * 2;         // 0..62 local
    const float4* xg = reinterpret_cast<const float4*>(
        x + ((size_t)b * (HG * HG) + (size_t)nt * NT) * DD);

    float acc0[4] = {0.f, 0.f, 0.f, 0.f};
    float acc1[4] = {0.f, 0.f, 0.f, 0.f};
    #pragma unroll
    for (int i = 0; i < DD / 4; i++) {
        float4 xa = __ldg(&xg[(size_t)n0 * 32 + i]);
        float4 xb = __ldg(&xg[(size_t)(n0 + 1) * 32 + i]);
        #pragma unroll
        for (int j = 0; j < 4; j++) {
            float4 w = *reinterpret_cast<const float4*>(&ws[(pg + 4 * j) * 132 + i * 4]);
            acc0[j] += xa.x * w.x + xa.y * w.y + xa.z * w.z + xa.w * w.w;
            acc1[j] += xb.x * w.x + xb.y * w.y + xb.z * w.z + xb.w * w.w;
        }
    }

    // store into expanded image layout y[b][h*4+j][w*4+pg]
    {
        int n  = nt * NT + n0;           // global n for row 0 of the pair
        int h0 = n >> 5, w0 = n & 31;
        int n1 = n + 1;
        int h1 = n1 >> 5, w1 = n1 & 31;
        float* yb = g_y + (size_t)b * (128 * 128);
        #pragma unroll
        for (int j = 0; j < 4; j++) {
            yb[(h0 * 4 + j) * 128 + w0 * 4 + pg] = acc0[j];
            yb[(h1 * 4 + j) * 128 + w1 * 4 + pg] = acc1[j];
        }
    }
}

// ---------------------------------------------------------------------------
// K2: out[b,c,row,col] = (y[b,row,col] + cb[c][pr*4..]) * mask[b,c]
//     256 threads: thread = (row_local, colf4). 1 coalesced LDG.128 from
//     L2-resident y, 16 perfectly coalesced independent STG.128 (one/channel).
// ---------------------------------------------------------------------------
__global__ void __launch_bounds__(256)
k2_broadcast(const float* __restrict__ mask,
             float* __restrict__ out) {
    __shared__ float cbs[CO * PPV];
    __shared__ float ms[CO];

    const int t  = threadIdx.x;
    const int rb = blockIdx.x;           // 0..15 : 8-row group
    const int b  = blockIdx.y;           // 0..31

    cbs[t] = g_cb[t];                    // 256 threads == 256 entries
    if (t < CO) ms[t] = mask[b * CO + t];
    __syncthreads();

    const int row   = rb * 8 + (t >> 5); // 0..127
    const int colf4 = t & 31;            // float4 index along width
    const int pr    = row & 3;           // patch row

    const float4 y4 = *reinterpret_cast<const float4*>(
        &g_y[((size_t)b * 128 + row) * 128 + colf4 * 4]);

    // compute all 16 channel values first -> independent store burst (MLP)
    float4 o[CO];
    #pragma unroll
    for (int c = 0; c < CO; c++) {
        float4 cb4 = *reinterpret_cast<const float4*>(&cbs[c * PPV + pr * 4]);
        float  m   = ms[c];
        o[c].x = (y4.x + cb4.x) * m;
        o[c].y = (y4.y + cb4.y) * m;
        o[c].z = (y4.z + cb4.z) * m;
        o[c].w = (y4.w + cb4.w) * m;
    }
    float* ob = out + (((size_t)b * CO) * 128 + row) * 128 + colf4 * 4;
    #pragma unroll
    for (int c = 0; c < CO; c++)
        *reinterpret_cast<float4*>(ob + (size_t)c * (128 * 128)) = o[c];
}

// ---------------------------------------------------------------------------
extern "C" void kernel_launch(void* const* d_in, const int* in_sizes, int n_in,
                              void* d_out, int out_size) {
    const float* x    = (const float*)d_in[0];   // (32, 1024, 128)
    const float* mask = (const float*)d_in[1];   // (32, 16)
    const float* emb  = (const float*)d_in[2];   // (256, 128)
    const float* W    = (const float*)d_in[3];   // (16, 128)
    const float* bias = (const float*)d_in[4];   // (16,)
    float* out = (float*)d_out;                  // (32, 16, 128, 128)

    dim3 g1(HG * HG / NT, NB);                   // (16, 32)
    k1_gemv<<<g1, 128>>>(x, W, emb, bias);
    dim3 g2(16, NB);                             // (16, 32)
    k2_broadcast<<<g2, 256>>>(mask, out);
}